// round 6
// baseline (speedup 1.0000x reference)
#include <cuda_runtime.h>
#include <cstdint>

#define NROWS 50000
#define DIM   128
#define FILT  128
#define RB    20
#define P_EDGES 1600000

// scratch (device globals: no allocation allowed)
__device__ float g_h[NROWS * FILT];
__device__ float g_agg[NROWS * FILT];
__device__ float g_WinT[DIM * FILT];   // [k=d][oc=f]
__device__ float g_WoutT[FILT * DIM];  // [k=f][oc=d]

__device__ __forceinline__ float sspf(float x) {
    // softplus(x) - ln2, fast path. For x>15, log1p(exp(x)) ~= x (err < 3e-7)
    float r = __logf(1.0f + __expf(x));
    r = (x > 15.0f) ? x : r;
    return r - 0.69314718055994530942f;
}

// ---------------------------------------------------------------------------
// transpose both 128x128 weight matrices into [k][oc] layout
// ---------------------------------------------------------------------------
__global__ void transpose2_kernel(const float* __restrict__ Win,
                                  const float* __restrict__ Wout) {
    int i = blockIdx.x * blockDim.x + threadIdx.x;
    if (i < 128 * 128) {
        int oc = i >> 7, k = i & 127;
        g_WinT[k * 128 + oc]  = Win[oc * 128 + k];
        g_WoutT[k * 128 + oc] = Wout[oc * 128 + k];
    }
}

__global__ void zero_agg_kernel() {
    int i = blockIdx.x * blockDim.x + threadIdx.x;
    int stride = gridDim.x * blockDim.x;
    float4 z = make_float4(0.f, 0.f, 0.f, 0.f);
    float4* p = reinterpret_cast<float4*>(g_agg);
    for (; i < NROWS * FILT / 4; i += stride) p[i] = z;
}

// ---------------------------------------------------------------------------
// GEMM: C[n, oc] = act( sum_k A[n,k] * WT[k,oc] + bias[oc] )
// A: [nrows,128], WT: [128,128] (k-major). Block tile 64x128, thread tile 8x4.
// ---------------------------------------------------------------------------
template <bool SSP>
__global__ __launch_bounds__(256) void gemm_kernel(const float* __restrict__ A,
                                                   const float* __restrict__ WT,
                                                   const float* __restrict__ bias,
                                                   float* __restrict__ C,
                                                   int nrows) {
    __shared__ float As[64][32];
    __shared__ float Ws[32][128];

    int tid  = threadIdx.x;
    int warp = tid >> 5;
    int lane = tid & 31;
    int gr0  = blockIdx.x * 64;
    int r0   = warp * 8;
    int c0   = lane * 4;

    float4 acc[8];
#pragma unroll
    for (int i = 0; i < 8; i++) acc[i] = make_float4(0.f, 0.f, 0.f, 0.f);

    for (int k0 = 0; k0 < 128; k0 += 32) {
        // stage A tile: 64 rows x 32 k = 512 float4
#pragma unroll
        for (int v = 0; v < 2; v++) {
            int fi  = tid + v * 256;   // 0..511
            int row = fi >> 3;
            int kq  = fi & 7;
            int grow = gr0 + row;
            float4 val = make_float4(0.f, 0.f, 0.f, 0.f);
            if (grow < nrows)
                val = *reinterpret_cast<const float4*>(A + (size_t)grow * 128 + k0 + kq * 4);
            *reinterpret_cast<float4*>(&As[row][kq * 4]) = val;
        }
        // stage W tile: 32 k x 128 oc = 1024 float4
#pragma unroll
        for (int v = 0; v < 4; v++) {
            int fi = tid + v * 256;    // 0..1023
            int kr = fi >> 5;
            int f4 = fi & 31;
            *reinterpret_cast<float4*>(&Ws[kr][f4 * 4]) =
                *reinterpret_cast<const float4*>(WT + (size_t)(k0 + kr) * 128 + f4 * 4);
        }
        __syncthreads();

#pragma unroll
        for (int kk = 0; kk < 32; kk++) {
            float4 bv = *reinterpret_cast<const float4*>(&Ws[kk][c0]);
#pragma unroll
            for (int i = 0; i < 8; i++) {
                float a = As[r0 + i][kk];   // broadcast LDS
                acc[i].x = fmaf(a, bv.x, acc[i].x);
                acc[i].y = fmaf(a, bv.y, acc[i].y);
                acc[i].z = fmaf(a, bv.z, acc[i].z);
                acc[i].w = fmaf(a, bv.w, acc[i].w);
            }
        }
        __syncthreads();
    }

    float4 bb = *reinterpret_cast<const float4*>(bias + c0);
#pragma unroll
    for (int i = 0; i < 8; i++) {
        int grow = gr0 + r0 + i;
        if (grow < nrows) {
            float4 o;
            o.x = acc[i].x + bb.x;
            o.y = acc[i].y + bb.y;
            o.z = acc[i].z + bb.z;
            o.w = acc[i].w + bb.w;
            if (SSP) {
                o.x = sspf(o.x); o.y = sspf(o.y);
                o.z = sspf(o.z); o.w = sspf(o.w);
            }
            *reinterpret_cast<float4*>(C + (size_t)grow * 128 + c0) = o;
        }
    }
}

// ---------------------------------------------------------------------------
// Edge kernel: one warp per edge (grid-stride), lane owns 4 consecutive filters.
// Filter weights register-resident per lane (amortized over many edges).
// References g_h / g_agg as device symbols (correct device addresses).
// ---------------------------------------------------------------------------
__global__ __launch_bounds__(256) void edge_kernel(const float* __restrict__ f_ij,
                                                   const int* __restrict__ idx_i,
                                                   const int* __restrict__ idx_j,
                                                   const float* __restrict__ rcut,
                                                   const float* __restrict__ W_filter,
                                                   const float* __restrict__ b_filter) {
    int lane  = threadIdx.x & 31;
    int gwarp = (blockIdx.x * blockDim.x + threadIdx.x) >> 5;
    int nwarp = (gridDim.x * blockDim.x) >> 5;
    int f0    = lane * 4;

    float w[4][RB];
    float bb[4];
#pragma unroll
    for (int j = 0; j < 4; j++) {
        bb[j] = __ldg(b_filter + f0 + j);
#pragma unroll
        for (int r = 0; r < RB; r++)
            w[j][r] = __ldg(W_filter + (size_t)(f0 + j) * RB + r);
    }

    for (int p = gwarp; p < P_EDGES; p += nwarp) {
        int   ji = __ldg(idx_j + p);
        int   ii = __ldg(idx_i + p);
        float rc = __ldg(rcut + p);

        const float4* fr = reinterpret_cast<const float4*>(f_ij + (size_t)p * RB);
        float4 q0 = __ldg(fr + 0);
        float4 q1 = __ldg(fr + 1);
        float4 q2 = __ldg(fr + 2);
        float4 q3 = __ldg(fr + 3);
        float4 q4 = __ldg(fr + 4);
        float fv[RB];
        fv[0]=q0.x; fv[1]=q0.y; fv[2]=q0.z; fv[3]=q0.w;
        fv[4]=q1.x; fv[5]=q1.y; fv[6]=q1.z; fv[7]=q1.w;
        fv[8]=q2.x; fv[9]=q2.y; fv[10]=q2.z; fv[11]=q2.w;
        fv[12]=q3.x; fv[13]=q3.y; fv[14]=q3.z; fv[15]=q3.w;
        fv[16]=q4.x; fv[17]=q4.y; fv[18]=q4.z; fv[19]=q4.w;

        float a0 = bb[0], a1 = bb[1], a2 = bb[2], a3 = bb[3];
#pragma unroll
        for (int r = 0; r < RB; r++) {
            a0 = fmaf(fv[r], w[0][r], a0);
            a1 = fmaf(fv[r], w[1][r], a1);
            a2 = fmaf(fv[r], w[2][r], a2);
            a3 = fmaf(fv[r], w[3][r], a3);
        }

        float4 hv = *reinterpret_cast<const float4*>(g_h + (size_t)ji * FILT + f0);
        float ox = sspf(a0) * rc * hv.x;
        float oy = sspf(a1) * rc * hv.y;
        float oz = sspf(a2) * rc * hv.z;
        float ow = sspf(a3) * rc * hv.w;

        float* dst = g_agg + (size_t)ii * FILT + f0;
        asm volatile("red.global.add.v4.f32 [%0], {%1, %2, %3, %4};"
                     :: "l"(dst), "f"(ox), "f"(oy), "f"(oz), "f"(ow)
                     : "memory");
    }
}

// ---------------------------------------------------------------------------
// Launch. CRITICAL FIX: __device__ globals passed as kernel arguments must be
// resolved via cudaGetSymbolAddress — referencing the symbol in host code
// yields the HOST shadow address (silently dereferenceable on GB300 via
// NVLink-C2C ATS => reads zeros instead of faulting).
// ---------------------------------------------------------------------------
extern "C" void kernel_launch(void* const* d_in, const int* in_sizes, int n_in,
                              void* d_out, int out_size) {
    int ix = -1, ifij = -1, iwf = -1;
    int i16k[4]; int n16k = 0;       // W_in, W_out (16384 elems each)
    int i1m6[4]; int n1m6 = 0;       // idx_i, idx_j, rcut_ij (1.6M each)
    int i128[4]; int n128 = 0;       // b_in, b_filter, b_out (128 each)

    for (int i = 0; i < n_in; i++) {
        long s = in_sizes[i];
        if      (s == 6400000)  ix   = i;              // x [1,50000,128]
        else if (s == 32000000) ifij = i;              // f_ij [P,20]
        else if (s == 2560)     iwf  = i;              // W_filter [128,20]
        else if (s == 16384)  { if (n16k < 4) i16k[n16k++] = i; }
        else if (s == 1600000){ if (n1m6 < 4) i1m6[n1m6++] = i; }
        else if (s == 128)    { if (n128 < 4) i128[n128++] = i; }
    }

    const float* x        = (const float*)d_in[ix];
    const float* f_ij     = (const float*)d_in[ifij];
    const float* W_filter = (const float*)d_in[iwf];
    const int*   idx_i    = (const int*)d_in[i1m6[0]];
    const int*   idx_j    = (const int*)d_in[i1m6[1]];
    const float* rcut_ij  = (const float*)d_in[i1m6[2]];
    const float* W_in     = (const float*)d_in[i16k[0]];
    const float* W_out    = (const float*)d_in[i16k[1]];
    bool sorted_keys = (i128[0] < ifij);
    const float* b_in     = (const float*)d_in[sorted_keys ? i128[1] : i128[0]];
    const float* b_filter = (const float*)d_in[sorted_keys ? i128[0] : i128[1]];
    const float* b_out    = (const float*)d_in[i128[2]];

    float* out = (float*)d_out;

    // Resolve REAL device addresses of scratch globals (host query, no alloc,
    // executes immediately — safe under graph capture).
    void *p_h, *p_agg, *p_WinT, *p_WoutT;
    cudaGetSymbolAddress(&p_h,     g_h);
    cudaGetSymbolAddress(&p_agg,   g_agg);
    cudaGetSymbolAddress(&p_WinT,  g_WinT);
    cudaGetSymbolAddress(&p_WoutT, g_WoutT);
    float* dev_h     = (float*)p_h;
    float* dev_agg   = (float*)p_agg;
    float* dev_WinT  = (float*)p_WinT;
    float* dev_WoutT = (float*)p_WoutT;

    // 1. transpose weights (k-major for GEMM)
    transpose2_kernel<<<64, 256>>>(W_in, W_out);

    // 2. h = x @ W_in^T + b_in
    gemm_kernel<false><<<(NROWS + 63) / 64, 256>>>(x, dev_WinT, b_in, dev_h, NROWS);

    // 3. zero accumulator
    zero_agg_kernel<<<1024, 256>>>();

    // 4. fused filter-net + gather + scatter-add
    edge_kernel<<<1184, 256>>>(f_ij, idx_i, idx_j, rcut_ij, W_filter, b_filter);

    // 5. out = ssp(agg @ W_out^T + b_out)
    gemm_kernel<true><<<(NROWS + 63) / 64, 256>>>(dev_agg, dev_WoutT, b_out, out, NROWS);
}